// round 16
// baseline (speedup 1.0000x reference)
#include <cuda_runtime.h>
#include <cuda_fp16.h>

// Problem-fixed dims: N=100000, E=1600000, IN=128, H=64, OUT=32
#define MAXN 100000
#define MAXE 1600000
#define IN_DIM 128
#define H_DIM 64
#define OUT_DIM 32
#define SCAN_B 1024
#define MAX_BLK ((MAXN + SCAN_B - 1) / SCAN_B)   // 98

typedef unsigned long long ull;

// ---------------- scratch (device globals; no allocation allowed) ------------
__device__ __align__(16) int   g_cnt [MAXN];   // zero at load; re-zeroed by k_scatter
__device__ __align__(16) int   g_row [MAXN + 1];
__device__ __align__(16) int   g_cur [MAXN];
__device__ __align__(16) int   g_bsum[MAX_BLK];
__device__ __align__(16) float g_dinv[MAXN];
__device__ __align__(16) int2  g_csr [MAXE];   // (src, norm-bits) grouped by dst
__device__ __align__(16) __half g_Z1h[(size_t)MAXN * H_DIM]; // x@W1      (fp16)
__device__ __align__(16) float  g_h [(size_t)MAXN * H_DIM];  // conv1 out (fp32)
__device__ __align__(16) __half g_Z2h[(size_t)MAXN * H_DIM]; // relu(h)@W (fp16)

// ---------------- bit-cast helpers -------------------------------------------
__device__ __forceinline__ unsigned h2u(__half2 h) {
    return *reinterpret_cast<unsigned*>(&h);
}
__device__ __forceinline__ __half2 u2h(unsigned u) {
    return *reinterpret_cast<__half2*>(&u);
}

// ---------------- f32x2 packed FMA helpers -----------------------------------
__device__ __forceinline__ ull pack_dup(float a) {
    ull r;
    asm("mov.b64 %0, {%1, %1};" : "=l"(r) : "r"(__float_as_uint(a)));
    return r;
}
#define FMA2(acc, a2, b2) \
    asm("fma.rn.f32x2 %0, %1, %2, %0;" : "+l"(acc) : "l"(a2), "l"(b2))

__device__ __forceinline__ float2 unpack2(ull v) {
    float2 f;
    asm("mov.b64 {%0, %1}, %2;" : "=f"(f.x), "=f"(f.y) : "l"(v));
    return f;
}

// Convert 32 packed-f32x2 accumulators to a 64-col fp16 row and store.
__device__ __forceinline__ void store_row_fp16(__half* dst, const ull* acc) {
    uint4* crow = (uint4*)dst;
#pragma unroll
    for (int q = 0; q < 8; q++) {
        uint4 v;
        float2 f0 = unpack2(acc[4 * q + 0]);
        float2 f1 = unpack2(acc[4 * q + 1]);
        float2 f2 = unpack2(acc[4 * q + 2]);
        float2 f3 = unpack2(acc[4 * q + 3]);
        v.x = h2u(__floats2half2_rn(f0.x, f0.y));
        v.y = h2u(__floats2half2_rn(f1.x, f1.y));
        v.z = h2u(__floats2half2_rn(f2.x, f2.y));
        v.w = h2u(__floats2half2_rn(f3.x, f3.y));
        crow[q] = v;
    }
}

// unpack uint4 (8 halves) into 8 floats
__device__ __forceinline__ void u4_to_f8(uint4 z, float* f) {
    float2 a = __half22float2(u2h(z.x));
    float2 b = __half22float2(u2h(z.y));
    float2 c = __half22float2(u2h(z.z));
    float2 d = __half22float2(u2h(z.w));
    f[0] = a.x; f[1] = a.y; f[2] = b.x; f[3] = b.y;
    f[4] = c.x; f[5] = c.y; f[6] = d.x; f[7] = d.y;
}

// ---------------- dtype probe helper (per-block, L2-hot, ~free) --------------
__device__ __forceinline__ int probe_is64(const int* __restrict__ raw, int E,
                                          int* sh_nz) {
    if (threadIdx.x == 0) *sh_nz = 0;
    __syncthreads();
    int K = 2048;
    if (K > 2 * E) K = 2 * E;
    int cnt = 0;
    for (int i = 2 * threadIdx.x + 1; i < K; i += 2 * blockDim.x)
        if (raw[i] != 0) cnt++;
    if (cnt) atomicAdd(sh_nz, cnt);
    __syncthreads();
    return (*sh_nz == 0);
}

// ---------------- count in-degrees straight from raw edge list ---------------
__global__ __launch_bounds__(256) void k_count(const int* __restrict__ raw,
                                               int E, int n) {
    __shared__ int nz;
    int is64 = probe_is64(raw, E, &nz);
    int i = blockIdx.x * 256 + threadIdx.x;
    if (i >= E) return;
    int d = is64 ? (int)((const long long*)raw)[(size_t)E + i] : raw[E + i];
    if ((unsigned)d >= (unsigned)n) d = 0;
    atomicAdd(&g_cnt[d], 1);
}

// ---------------- scan phase A: per-block scan, block totals -----------------
__global__ __launch_bounds__(SCAN_B) void k_scanA(int n) {
    __shared__ int sh[SCAN_B];
    int t = threadIdx.x;
    int i = blockIdx.x * SCAN_B + t;
    int v = (i < n) ? g_cnt[i] : 0;
    sh[t] = v;
    __syncthreads();
#pragma unroll
    for (int off = 1; off < SCAN_B; off <<= 1) {
        int u = (t >= off) ? sh[t - off] : 0;
        __syncthreads();
        sh[t] += u;
        __syncthreads();
    }
    if (i < n) g_row[i] = sh[t] - v;
    if (t == SCAN_B - 1) g_bsum[blockIdx.x] = sh[t];
}

// ---------------- scan phase C: self-computed block prefix + dinv ------------
// Each block sums g_bsum[0..blk-1] itself (<=98 L2-hot ints) - no phase B.
__global__ __launch_bounds__(SCAN_B) void k_scanC(int n, int nblk) {
    __shared__ int ssum[128];
    int t = threadIdx.x;
    if (t < 128)
        ssum[t] = (t < nblk && t < (int)blockIdx.x) ? g_bsum[t] : 0;
    __syncthreads();
#pragma unroll
    for (int off = 64; off >= 1; off >>= 1) {
        if (t < off) ssum[t] += ssum[t + off];
        __syncthreads();
    }
    int base = ssum[0];
    if (t == 0 && (int)blockIdx.x == nblk - 1)
        g_row[n] = base + g_bsum[blockIdx.x];   // grand total
    int i = blockIdx.x * SCAN_B + t;
    if (i < n) {
        int r = g_row[i] + base;
        g_row[i] = r;
        g_cur[i] = r;
        g_dinv[i] = rsqrtf(1.0f + (float)g_cnt[i]);  // +1 self-loop
    }
}

// ---------------- scatter into CSR; also reset g_cnt for next replay ---------
__global__ __launch_bounds__(256) void k_scatter(const int* __restrict__ raw,
                                                 int E, int n) {
    __shared__ int nz;
    int is64 = probe_is64(raw, E, &nz);
    int i = blockIdx.x * 256 + threadIdx.x;
    if (i < n) g_cnt[i] = 0;       // g_cnt no longer needed this run
    if (i >= E) return;
    int s, d;
    if (is64) {
        const long long* e64 = (const long long*)raw;
        s = (int)e64[i];
        d = (int)e64[(size_t)E + i];
    } else {
        s = raw[i];
        d = raw[E + i];
    }
    if ((unsigned)s >= (unsigned)n) s = 0;
    if ((unsigned)d >= (unsigned)n) d = 0;
    float w = g_dinv[s] * g_dinv[d];
    int pos = atomicAdd(&g_cur[d], 1);
    g_csr[pos] = make_int2(s, __float_as_int(w));
}

// ---------------- GEMM1: Z1 = x @ W1, 2 rows/thread, fp16 store --------------
__global__ __launch_bounds__(128) void k_gemm1(const float* __restrict__ x,
                                               const float* __restrict__ W1, int n) {
    __shared__ __align__(16) float Bs[IN_DIM * H_DIM];  // 32 KB
    int tid = threadIdx.x;
    for (int i = tid; i < IN_DIM * H_DIM; i += 128) Bs[i] = W1[i];
    __syncthreads();
    int rA = blockIdx.x * 256 + tid;
    if (rA >= n) return;
    int rB = rA + 128;
    bool hasB = (rB < n);

    ull accA[32], accB[32];
#pragma unroll
    for (int i = 0; i < 32; i++) { accA[i] = 0ull; accB[i] = 0ull; }

    const float4* aA = (const float4*)(x + (size_t)rA * IN_DIM);
    const float4* aB = (const float4*)(x + (size_t)(hasB ? rB : rA) * IN_DIM);
    for (int k4 = 0; k4 < IN_DIM / 4; k4++) {
        float4 a4A = aA[k4];
        float4 a4B = aB[k4];
        float avA[4] = {a4A.x, a4A.y, a4A.z, a4A.w};
        float avB[4] = {a4B.x, a4B.y, a4B.z, a4B.w};
#pragma unroll
        for (int kk = 0; kk < 4; kk++) {
            ull a2A = pack_dup(avA[kk]);
            ull a2B = pack_dup(avB[kk]);
            const ull* br = (const ull*)(Bs + (k4 * 4 + kk) * H_DIM);
#pragma unroll
            for (int c = 0; c < 32; c++) {
                ull b = br[c];                 // one LDS feeds two rows
                FMA2(accA[c], a2A, b);
                FMA2(accB[c], a2B, b);
            }
        }
    }
    store_row_fp16(g_Z1h + (size_t)rA * H_DIM, accA);
    if (hasB) store_row_fp16(g_Z1h + (size_t)rB * H_DIM, accB);
}

// ---------------- CSR aggregation 1: warp/node, 4 edges/iter -----------------
// Quarter-warps own alternating edges; lane loads uint4 = 8 fp16 cols.
__global__ __launch_bounds__(256) void k_agg1_csr(const float* __restrict__ b1, int n) {
    int warp = (blockIdx.x * 256 + threadIdx.x) >> 5;
    int lane = threadIdx.x & 31;
    if (warp >= n) return;
    int q = lane >> 3, l8 = lane & 7;
    int rs = g_row[warp], re = g_row[warp + 1];
    const uint4* zb = (const uint4*)g_Z1h;   // 8 halves per uint4, 8 per row

    float acc[8];
    if (q == 0) {   // seed self-loop + bias once
        float dv = g_dinv[warp];
        float s2 = dv * dv;
        float f[8];
        u4_to_f8(zb[(size_t)warp * 8 + l8], f);
        const float2* b2 = (const float2*)b1;
#pragma unroll
        for (int j = 0; j < 4; j++) {
            float2 b = b2[l8 * 4 + j];
            acc[2 * j]     = fmaf(f[2 * j],     s2, b.x);
            acc[2 * j + 1] = fmaf(f[2 * j + 1], s2, b.y);
        }
    } else {
#pragma unroll
        for (int j = 0; j < 8; j++) acc[j] = 0.f;
    }
    for (int e = rs + q; e < re; e += 4) {
        int2 ed = g_csr[e];
        float w = __int_as_float(ed.y);
        float f[8];
        u4_to_f8(zb[(size_t)ed.x * 8 + l8], f);
#pragma unroll
        for (int j = 0; j < 8; j++) acc[j] = fmaf(w, f[j], acc[j]);
    }
#pragma unroll
    for (int j = 0; j < 8; j++) {
        acc[j] += __shfl_xor_sync(0xffffffffu, acc[j], 8);
        acc[j] += __shfl_xor_sync(0xffffffffu, acc[j], 16);
    }
    if (q == 0) {   // lanes 0..7 write 8 cols each (two float4)
        float4* out = (float4*)(g_h + (size_t)warp * H_DIM + l8 * 8);
        out[0] = make_float4(acc[0], acc[1], acc[2], acc[3]);
        out[1] = make_float4(acc[4], acc[5], acc[6], acc[7]);
    }
}

// ---------------- GEMM2: Z2 = relu(h) @ [Wmu|Wlog], 2 rows/thread ------------
__global__ __launch_bounds__(128) void k_gemm2(const float* __restrict__ Wmu,
                                               const float* __restrict__ Wlog, int n) {
    __shared__ __align__(16) float Bs[H_DIM * 64];  // cols 0..31 Wmu, 32..63 Wlog
    int tid = threadIdx.x;
    for (int i = tid; i < H_DIM * OUT_DIM; i += 128) {
        int k = i / OUT_DIM, c = i % OUT_DIM;
        Bs[k * 64 + c]      = Wmu[i];
        Bs[k * 64 + 32 + c] = Wlog[i];
    }
    __syncthreads();
    int rA = blockIdx.x * 256 + tid;
    if (rA >= n) return;
    int rB = rA + 128;
    bool hasB = (rB < n);

    ull accA[32], accB[32];
#pragma unroll
    for (int i = 0; i < 32; i++) { accA[i] = 0ull; accB[i] = 0ull; }

    const float4* aA = (const float4*)(g_h + (size_t)rA * H_DIM);
    const float4* aB = (const float4*)(g_h + (size_t)(hasB ? rB : rA) * H_DIM);
    for (int k4 = 0; k4 < H_DIM / 4; k4++) {
        float4 a4A = aA[k4];
        float4 a4B = aB[k4];
        float avA[4] = {fmaxf(a4A.x, 0.f), fmaxf(a4A.y, 0.f),
                        fmaxf(a4A.z, 0.f), fmaxf(a4A.w, 0.f)};
        float avB[4] = {fmaxf(a4B.x, 0.f), fmaxf(a4B.y, 0.f),
                        fmaxf(a4B.z, 0.f), fmaxf(a4B.w, 0.f)};
#pragma unroll
        for (int kk = 0; kk < 4; kk++) {
            ull a2A = pack_dup(avA[kk]);
            ull a2B = pack_dup(avB[kk]);
            const ull* br = (const ull*)(Bs + (k4 * 4 + kk) * 64);
#pragma unroll
            for (int c = 0; c < 32; c++) {
                ull b = br[c];
                FMA2(accA[c], a2A, b);
                FMA2(accB[c], a2B, b);
            }
        }
    }
    store_row_fp16(g_Z2h + (size_t)rA * H_DIM, accA);
    if (hasB) store_row_fp16(g_Z2h + (size_t)rB * H_DIM, accB);
}

// ---------------- CSR aggregation 2: warp/node, 4 edges/iter -> d_out --------
__global__ __launch_bounds__(256) void k_agg2_csr(const float* __restrict__ bmu,
                                                  const float* __restrict__ blog,
                                                  float* __restrict__ outMu,
                                                  float* __restrict__ outLog, int n) {
    int warp = (blockIdx.x * 256 + threadIdx.x) >> 5;
    int lane = threadIdx.x & 31;
    if (warp >= n) return;
    int q = lane >> 3, l8 = lane & 7;
    int rs = g_row[warp], re = g_row[warp + 1];
    const uint4* zb = (const uint4*)g_Z2h;

    float acc[8];
    if (q == 0) {
        float dv = g_dinv[warp];
        float s2 = dv * dv;
        float f[8];
        u4_to_f8(zb[(size_t)warp * 8 + l8], f);
        // lane l8 owns cols 8*l8..8*l8+7: l8<4 -> mu cols, l8>=4 -> log cols
        const float2* b2 = (l8 < 4) ? (const float2*)bmu : (const float2*)blog;
        int boff = (l8 & 3) * 4;
#pragma unroll
        for (int j = 0; j < 4; j++) {
            float2 b = b2[boff + j];
            acc[2 * j]     = fmaf(f[2 * j],     s2, b.x);
            acc[2 * j + 1] = fmaf(f[2 * j + 1], s2, b.y);
        }
    } else {
#pragma unroll
        for (int j = 0; j < 8; j++) acc[j] = 0.f;
    }
    for (int e = rs + q; e < re; e += 4) {
        int2 ed = g_csr[e];
        float w = __int_as_float(ed.y);
        float f[8];
        u4_to_f8(zb[(size_t)ed.x * 8 + l8], f);
#pragma unroll
        for (int j = 0; j < 8; j++) acc[j] = fmaf(w, f[j], acc[j]);
    }
#pragma unroll
    for (int j = 0; j < 8; j++) {
        acc[j] += __shfl_xor_sync(0xffffffffu, acc[j], 8);
        acc[j] += __shfl_xor_sync(0xffffffffu, acc[j], 16);
    }
    if (q == 0) {
        float* base = (l8 < 4) ? (outMu + (size_t)warp * OUT_DIM + l8 * 8)
                               : (outLog + (size_t)warp * OUT_DIM + (l8 - 4) * 8);
        ((float4*)base)[0] = make_float4(acc[0], acc[1], acc[2], acc[3]);
        ((float4*)base)[1] = make_float4(acc[4], acc[5], acc[6], acc[7]);
    }
}

// ---------------- launch -----------------------------------------------------
extern "C" void kernel_launch(void* const* d_in, const int* in_sizes, int n_in,
                              void* d_out, int out_size) {
    const float* x    = (const float*)d_in[0];
    const int*   eraw = (const int*)d_in[1];
    const float* W1   = (const float*)d_in[2];
    const float* b1   = (const float*)d_in[3];
    const float* Wmu  = (const float*)d_in[4];
    const float* bmu  = (const float*)d_in[5];
    const float* Wlog = (const float*)d_in[6];
    const float* blog = (const float*)d_in[7];

    int N = in_sizes[0] / IN_DIM;   // 100000
    int E = in_sizes[1] / 2;        // 1600000
    if (N > MAXN) N = MAXN;
    if (E > MAXE) E = MAXE;

    float* outMu  = (float*)d_out;
    float* outLog = (float*)d_out + (size_t)N * OUT_DIM;

    const int T = 256;
    int gE   = (E + T - 1) / T;
    int gW   = (N * 32 + T - 1) / T;          // warp-per-node grids
    int gG   = (N + 255) / 256;               // 2-row GEMM grids (128 threads)
    int nblk = (N + SCAN_B - 1) / SCAN_B;     // scan blocks (98)

    // Lazy side-stream + fork/join events (host objects only).
    static cudaStream_t s2 = nullptr;
    static cudaEvent_t  evFork = nullptr, evJoin = nullptr;
    if (s2 == nullptr) {
        cudaStreamCreateWithFlags(&s2, cudaStreamNonBlocking);
        cudaEventCreateWithFlags(&evFork, cudaEventDisableTiming);
        cudaEventCreateWithFlags(&evJoin, cudaEventDisableTiming);
    }

    // Fork: GEMM1 runs concurrently with the CSR build chain.
    cudaEventRecord(evFork, 0);
    cudaStreamWaitEvent(s2, evFork, 0);
    k_gemm1<<<gG, 128, 0, s2>>>(x, W1, N);
    cudaEventRecord(evJoin, s2);

    // CSR build on the main stream
    k_count<<<gE, T>>>(eraw, E, N);
    k_scanA<<<nblk, SCAN_B>>>(N);
    k_scanC<<<nblk, SCAN_B>>>(N, nblk);       // block-prefix + g_cur + dinv fused
    k_scatter<<<gE, T>>>(eraw, E, N);         // also resets g_cnt

    // Join: agg1 needs both Z1 (s2) and CSR (main stream)
    cudaStreamWaitEvent(0, evJoin, 0);

    // layer 1 aggregation
    k_agg1_csr<<<gW, T>>>(b1, N);

    // layer 2 (mu|log fused), aggregation writes d_out directly
    k_gemm2<<<gG, 128>>>(Wmu, Wlog, N);
    k_agg2_csr<<<gW, T>>>(bmu, blog, outMu, outLog, N);
}

// round 17
// speedup vs baseline: 1.3893x; 1.3893x over previous
#include <cuda_runtime.h>
#include <cuda_fp16.h>

// Problem-fixed dims: N=100000, E=1600000, IN=128, H=64, OUT=32
#define MAXN 100000
#define MAXE 1600000
#define IN_DIM 128
#define H_DIM 64
#define OUT_DIM 32
#define SCAN_B 1024
#define MAX_BLK ((MAXN + SCAN_B - 1) / SCAN_B)   // 98

typedef unsigned long long ull;

// ---------------- scratch (device globals; no allocation allowed) ------------
__device__ __align__(16) int   g_cnt [MAXN];   // zero at load; re-zeroed by k_scatter
__device__ __align__(16) int   g_row [MAXN + 1];
__device__ __align__(16) int   g_cur [MAXN];
__device__ __align__(16) int   g_bsum[MAX_BLK];
__device__ __align__(16) float g_dinv[MAXN];
__device__ __align__(16) int2  g_csr [MAXE];   // (src, norm-bits) grouped by dst
__device__ __align__(16) __half g_Z1h[(size_t)MAXN * H_DIM]; // x@W1      (fp16)
__device__ __align__(16) float  g_h [(size_t)MAXN * H_DIM];  // conv1 out (fp32)
__device__ __align__(16) __half g_Z2h[(size_t)MAXN * H_DIM]; // relu(h)@W (fp16)

// ---------------- bit-cast helpers -------------------------------------------
__device__ __forceinline__ unsigned h2u(__half2 h) {
    return *reinterpret_cast<unsigned*>(&h);
}
__device__ __forceinline__ __half2 u2h(unsigned u) {
    return *reinterpret_cast<__half2*>(&u);
}

// ---------------- f32x2 packed FMA helpers -----------------------------------
__device__ __forceinline__ ull pack_dup(float a) {
    ull r;
    asm("mov.b64 %0, {%1, %1};" : "=l"(r) : "r"(__float_as_uint(a)));
    return r;
}
#define FMA2(acc, a2, b2) \
    asm("fma.rn.f32x2 %0, %1, %2, %0;" : "+l"(acc) : "l"(a2), "l"(b2))

__device__ __forceinline__ float2 unpack2(ull v) {
    float2 f;
    asm("mov.b64 {%0, %1}, %2;" : "=f"(f.x), "=f"(f.y) : "l"(v));
    return f;
}

// Convert 32 packed-f32x2 accumulators to a 64-col fp16 row and store.
__device__ __forceinline__ void store_row_fp16(__half* dst, const ull* acc) {
    uint4* crow = (uint4*)dst;
#pragma unroll
    for (int q = 0; q < 8; q++) {
        uint4 v;
        float2 f0 = unpack2(acc[4 * q + 0]);
        float2 f1 = unpack2(acc[4 * q + 1]);
        float2 f2 = unpack2(acc[4 * q + 2]);
        float2 f3 = unpack2(acc[4 * q + 3]);
        v.x = h2u(__floats2half2_rn(f0.x, f0.y));
        v.y = h2u(__floats2half2_rn(f1.x, f1.y));
        v.z = h2u(__floats2half2_rn(f2.x, f2.y));
        v.w = h2u(__floats2half2_rn(f3.x, f3.y));
        crow[q] = v;
    }
}

// ---------------- dtype probe helper (per-block, L2-hot, ~free) --------------
__device__ __forceinline__ int probe_is64(const int* __restrict__ raw, int E,
                                          int* sh_nz) {
    if (threadIdx.x == 0) *sh_nz = 0;
    __syncthreads();
    int K = 2048;
    if (K > 2 * E) K = 2 * E;
    int cnt = 0;
    for (int i = 2 * threadIdx.x + 1; i < K; i += 2 * blockDim.x)
        if (raw[i] != 0) cnt++;
    if (cnt) atomicAdd(sh_nz, cnt);
    __syncthreads();
    return (*sh_nz == 0);
}

// ---------------- count in-degrees straight from raw edge list ---------------
__global__ __launch_bounds__(256) void k_count(const int* __restrict__ raw,
                                               int E, int n) {
    __shared__ int nz;
    int is64 = probe_is64(raw, E, &nz);
    int i = blockIdx.x * 256 + threadIdx.x;
    if (i >= E) return;
    int d = is64 ? (int)((const long long*)raw)[(size_t)E + i] : raw[E + i];
    if ((unsigned)d >= (unsigned)n) d = 0;
    atomicAdd(&g_cnt[d], 1);
}

// ---------------- scan phase A: per-block scan, block totals -----------------
__global__ __launch_bounds__(SCAN_B) void k_scanA(int n) {
    __shared__ int sh[SCAN_B];
    int t = threadIdx.x;
    int i = blockIdx.x * SCAN_B + t;
    int v = (i < n) ? g_cnt[i] : 0;
    sh[t] = v;
    __syncthreads();
#pragma unroll
    for (int off = 1; off < SCAN_B; off <<= 1) {
        int u = (t >= off) ? sh[t - off] : 0;
        __syncthreads();
        sh[t] += u;
        __syncthreads();
    }
    if (i < n) g_row[i] = sh[t] - v;
    if (t == SCAN_B - 1) g_bsum[blockIdx.x] = sh[t];
}

// ---------------- scan phase C: self-computed block prefix + dinv ------------
// Each block sums g_bsum[0..blk-1] itself (<=98 L2-hot ints) - no phase B.
__global__ __launch_bounds__(SCAN_B) void k_scanC(int n, int nblk) {
    __shared__ int ssum[128];
    int t = threadIdx.x;
    if (t < 128)
        ssum[t] = (t < nblk && t < (int)blockIdx.x) ? g_bsum[t] : 0;
    __syncthreads();
#pragma unroll
    for (int off = 64; off >= 1; off >>= 1) {
        if (t < off) ssum[t] += ssum[t + off];
        __syncthreads();
    }
    int base = ssum[0];
    if (t == 0 && (int)blockIdx.x == nblk - 1)
        g_row[n] = base + g_bsum[blockIdx.x];   // grand total
    int i = blockIdx.x * SCAN_B + t;
    if (i < n) {
        int r = g_row[i] + base;
        g_row[i] = r;
        g_cur[i] = r;
        g_dinv[i] = rsqrtf(1.0f + (float)g_cnt[i]);  // +1 self-loop
    }
}

// ---------------- scatter into CSR; also reset g_cnt for next replay ---------
__global__ __launch_bounds__(256) void k_scatter(const int* __restrict__ raw,
                                                 int E, int n) {
    __shared__ int nz;
    int is64 = probe_is64(raw, E, &nz);
    int i = blockIdx.x * 256 + threadIdx.x;
    if (i < n) g_cnt[i] = 0;       // g_cnt no longer needed this run
    if (i >= E) return;
    int s, d;
    if (is64) {
        const long long* e64 = (const long long*)raw;
        s = (int)e64[i];
        d = (int)e64[(size_t)E + i];
    } else {
        s = raw[i];
        d = raw[E + i];
    }
    if ((unsigned)s >= (unsigned)n) s = 0;
    if ((unsigned)d >= (unsigned)n) d = 0;
    float w = g_dinv[s] * g_dinv[d];
    int pos = atomicAdd(&g_cur[d], 1);
    g_csr[pos] = make_int2(s, __float_as_int(w));
}

// ---------------- GEMM1: Z1 = x @ W1, 2 rows/thread, fp16 store --------------
__global__ __launch_bounds__(128) void k_gemm1(const float* __restrict__ x,
                                               const float* __restrict__ W1, int n) {
    __shared__ __align__(16) float Bs[IN_DIM * H_DIM];  // 32 KB
    int tid = threadIdx.x;
    for (int i = tid; i < IN_DIM * H_DIM; i += 128) Bs[i] = W1[i];
    __syncthreads();
    int rA = blockIdx.x * 256 + tid;
    if (rA >= n) return;
    int rB = rA + 128;
    bool hasB = (rB < n);

    ull accA[32], accB[32];
#pragma unroll
    for (int i = 0; i < 32; i++) { accA[i] = 0ull; accB[i] = 0ull; }

    const float4* aA = (const float4*)(x + (size_t)rA * IN_DIM);
    const float4* aB = (const float4*)(x + (size_t)(hasB ? rB : rA) * IN_DIM);
    for (int k4 = 0; k4 < IN_DIM / 4; k4++) {
        float4 a4A = aA[k4];
        float4 a4B = aB[k4];
        float avA[4] = {a4A.x, a4A.y, a4A.z, a4A.w};
        float avB[4] = {a4B.x, a4B.y, a4B.z, a4B.w};
#pragma unroll
        for (int kk = 0; kk < 4; kk++) {
            ull a2A = pack_dup(avA[kk]);
            ull a2B = pack_dup(avB[kk]);
            const ull* br = (const ull*)(Bs + (k4 * 4 + kk) * H_DIM);
#pragma unroll
            for (int c = 0; c < 32; c++) {
                ull b = br[c];                 // one LDS feeds two rows
                FMA2(accA[c], a2A, b);
                FMA2(accB[c], a2B, b);
            }
        }
    }
    store_row_fp16(g_Z1h + (size_t)rA * H_DIM, accA);
    if (hasB) store_row_fp16(g_Z1h + (size_t)rB * H_DIM, accB);
}

// ---------------- CSR aggregation 1: warp/node, 2 edges/iter, prefetch -------
__global__ __launch_bounds__(256) void k_agg1_csr(const float* __restrict__ b1, int n) {
    int warp = (blockIdx.x * 256 + threadIdx.x) >> 5;
    int lane = threadIdx.x & 31;
    if (warp >= n) return;
    int half = lane >> 4, l16 = lane & 15;
    int rs = g_row[warp], re = g_row[warp + 1];
    const uint2* zb = (const uint2*)g_Z1h;   // uint2 = 4 halves = 4 cols

    float4 acc;
    if (half == 0) {   // seed self-loop + bias once
        float dv = g_dinv[warp];
        float s2 = dv * dv;
        uint2 z = zb[(size_t)warp * 16 + l16];
        float2 f0 = __half22float2(u2h(z.x));
        float2 f1 = __half22float2(u2h(z.y));
        float4 b  = ((const float4*)b1)[l16];
        acc = make_float4(fmaf(f0.x, s2, b.x), fmaf(f0.y, s2, b.y),
                          fmaf(f1.x, s2, b.z), fmaf(f1.y, s2, b.w));
    } else {
        acc = make_float4(0.f, 0.f, 0.f, 0.f);
    }
    int e = rs + half;
    int2 ed = make_int2(0, 0);
    uint2 z  = make_uint2(0u, 0u);
    if (e < re) {
        ed = g_csr[e];
        z  = zb[(size_t)ed.x * 16 + l16];
    }
    while (e < re) {
        int en = e + 2;
        int2 edn = ed;
        uint2 zn = z;
        if (en < re) {                  // prefetch next edge before using current
            edn = g_csr[en];
            zn  = zb[(size_t)edn.x * 16 + l16];
        }
        float w = __int_as_float(ed.y);
        float2 f0 = __half22float2(u2h(z.x));
        float2 f1 = __half22float2(u2h(z.y));
        acc.x = fmaf(w, f0.x, acc.x);
        acc.y = fmaf(w, f0.y, acc.y);
        acc.z = fmaf(w, f1.x, acc.z);
        acc.w = fmaf(w, f1.y, acc.w);
        ed = edn; z = zn; e = en;
    }
    acc.x += __shfl_xor_sync(0xffffffffu, acc.x, 16);
    acc.y += __shfl_xor_sync(0xffffffffu, acc.y, 16);
    acc.z += __shfl_xor_sync(0xffffffffu, acc.z, 16);
    acc.w += __shfl_xor_sync(0xffffffffu, acc.w, 16);
    if (half == 0)
        ((float4*)g_h)[(size_t)warp * 16 + l16] = acc;
}

// ---------------- GEMM2: Z2 = relu(h) @ [Wmu|Wlog], 2 rows/thread ------------
__global__ __launch_bounds__(128) void k_gemm2(const float* __restrict__ Wmu,
                                               const float* __restrict__ Wlog, int n) {
    __shared__ __align__(16) float Bs[H_DIM * 64];  // cols 0..31 Wmu, 32..63 Wlog
    int tid = threadIdx.x;
    for (int i = tid; i < H_DIM * OUT_DIM; i += 128) {
        int k = i / OUT_DIM, c = i % OUT_DIM;
        Bs[k * 64 + c]      = Wmu[i];
        Bs[k * 64 + 32 + c] = Wlog[i];
    }
    __syncthreads();
    int rA = blockIdx.x * 256 + tid;
    if (rA >= n) return;
    int rB = rA + 128;
    bool hasB = (rB < n);

    ull accA[32], accB[32];
#pragma unroll
    for (int i = 0; i < 32; i++) { accA[i] = 0ull; accB[i] = 0ull; }

    const float4* aA = (const float4*)(g_h + (size_t)rA * H_DIM);
    const float4* aB = (const float4*)(g_h + (size_t)(hasB ? rB : rA) * H_DIM);
    for (int k4 = 0; k4 < H_DIM / 4; k4++) {
        float4 a4A = aA[k4];
        float4 a4B = aB[k4];
        float avA[4] = {fmaxf(a4A.x, 0.f), fmaxf(a4A.y, 0.f),
                        fmaxf(a4A.z, 0.f), fmaxf(a4A.w, 0.f)};
        float avB[4] = {fmaxf(a4B.x, 0.f), fmaxf(a4B.y, 0.f),
                        fmaxf(a4B.z, 0.f), fmaxf(a4B.w, 0.f)};
#pragma unroll
        for (int kk = 0; kk < 4; kk++) {
            ull a2A = pack_dup(avA[kk]);
            ull a2B = pack_dup(avB[kk]);
            const ull* br = (const ull*)(Bs + (k4 * 4 + kk) * 64);
#pragma unroll
            for (int c = 0; c < 32; c++) {
                ull b = br[c];
                FMA2(accA[c], a2A, b);
                FMA2(accB[c], a2B, b);
            }
        }
    }
    store_row_fp16(g_Z2h + (size_t)rA * H_DIM, accA);
    if (hasB) store_row_fp16(g_Z2h + (size_t)rB * H_DIM, accB);
}

// ---------------- CSR aggregation 2: warp/node, prefetch -> d_out ------------
__global__ __launch_bounds__(256) void k_agg2_csr(const float* __restrict__ bmu,
                                                  const float* __restrict__ blog,
                                                  float* __restrict__ outMu,
                                                  float* __restrict__ outLog, int n) {
    int warp = (blockIdx.x * 256 + threadIdx.x) >> 5;
    int lane = threadIdx.x & 31;
    if (warp >= n) return;
    int half = lane >> 4, l16 = lane & 15;
    int rs = g_row[warp], re = g_row[warp + 1];
    const uint2* zb = (const uint2*)g_Z2h;

    float4 acc;
    if (half == 0) {
        float dv = g_dinv[warp];
        float s2 = dv * dv;
        uint2 z = zb[(size_t)warp * 16 + l16];
        float2 f0 = __half22float2(u2h(z.x));
        float2 f1 = __half22float2(u2h(z.y));
        float4 b = (l16 < 8) ? ((const float4*)bmu)[l16]
                             : ((const float4*)blog)[l16 - 8];
        acc = make_float4(fmaf(f0.x, s2, b.x), fmaf(f0.y, s2, b.y),
                          fmaf(f1.x, s2, b.z), fmaf(f1.y, s2, b.w));
    } else {
        acc = make_float4(0.f, 0.f, 0.f, 0.f);
    }
    int e = rs + half;
    int2 ed = make_int2(0, 0);
    uint2 z  = make_uint2(0u, 0u);
    if (e < re) {
        ed = g_csr[e];
        z  = zb[(size_t)ed.x * 16 + l16];
    }
    while (e < re) {
        int en = e + 2;
        int2 edn = ed;
        uint2 zn = z;
        if (en < re) {
            edn = g_csr[en];
            zn  = zb[(size_t)edn.x * 16 + l16];
        }
        float w = __int_as_float(ed.y);
        float2 f0 = __half22float2(u2h(z.x));
        float2 f1 = __half22float2(u2h(z.y));
        acc.x = fmaf(w, f0.x, acc.x);
        acc.y = fmaf(w, f0.y, acc.y);
        acc.z = fmaf(w, f1.x, acc.z);
        acc.w = fmaf(w, f1.y, acc.w);
        ed = edn; z = zn; e = en;
    }
    acc.x += __shfl_xor_sync(0xffffffffu, acc.x, 16);
    acc.y += __shfl_xor_sync(0xffffffffu, acc.y, 16);
    acc.z += __shfl_xor_sync(0xffffffffu, acc.z, 16);
    acc.w += __shfl_xor_sync(0xffffffffu, acc.w, 16);
    if (half == 0) {
        if (l16 < 8)
            ((float4*)(outMu + (size_t)warp * OUT_DIM))[l16] = acc;
        else
            ((float4*)(outLog + (size_t)warp * OUT_DIM))[l16 - 8] = acc;
    }
}

// ---------------- launch -----------------------------------------------------
extern "C" void kernel_launch(void* const* d_in, const int* in_sizes, int n_in,
                              void* d_out, int out_size) {
    const float* x    = (const float*)d_in[0];
    const int*   eraw = (const int*)d_in[1];
    const float* W1   = (const float*)d_in[2];
    const float* b1   = (const float*)d_in[3];
    const float* Wmu  = (const float*)d_in[4];
    const float* bmu  = (const float*)d_in[5];
    const float* Wlog = (const float*)d_in[6];
    const float* blog = (const float*)d_in[7];

    int N = in_sizes[0] / IN_DIM;   // 100000
    int E = in_sizes[1] / 2;        // 1600000
    if (N > MAXN) N = MAXN;
    if (E > MAXE) E = MAXE;

    float* outMu  = (float*)d_out;
    float* outLog = (float*)d_out + (size_t)N * OUT_DIM;

    const int T = 256;
    int gE   = (E + T - 1) / T;
    int gW   = (N * 32 + T - 1) / T;          // warp-per-node grids
    int gG   = (N + 255) / 256;               // 2-row GEMM grids (128 threads)
    int nblk = (N + SCAN_B - 1) / SCAN_B;     // scan blocks (98)

    // Lazy side-stream + fork/join events (host objects only).
    static cudaStream_t s2 = nullptr;
    static cudaEvent_t  evFork = nullptr, evJoin = nullptr;
    if (s2 == nullptr) {
        cudaStreamCreateWithFlags(&s2, cudaStreamNonBlocking);
        cudaEventCreateWithFlags(&evFork, cudaEventDisableTiming);
        cudaEventCreateWithFlags(&evJoin, cudaEventDisableTiming);
    }

    // Fork: GEMM1 runs concurrently with the CSR build chain.
    cudaEventRecord(evFork, 0);
    cudaStreamWaitEvent(s2, evFork, 0);
    k_gemm1<<<gG, 128, 0, s2>>>(x, W1, N);
    cudaEventRecord(evJoin, s2);

    // CSR build on the main stream
    k_count<<<gE, T>>>(eraw, E, N);
    k_scanA<<<nblk, SCAN_B>>>(N);
    k_scanC<<<nblk, SCAN_B>>>(N, nblk);       // block-prefix + g_cur + dinv fused
    k_scatter<<<gE, T>>>(eraw, E, N);         // also resets g_cnt

    // Join: agg1 needs both Z1 (s2) and CSR (main stream)
    cudaStreamWaitEvent(0, evJoin, 0);

    // layer 1 aggregation
    k_agg1_csr<<<gW, T>>>(b1, N);

    // layer 2 (mu|log fused), aggregation writes d_out directly
    k_gemm2<<<gG, 128>>>(Wmu, Wlog, N);
    k_agg2_csr<<<gW, T>>>(bmu, blog, outMu, outLog, N);
}